// round 6
// baseline (speedup 1.0000x reference)
#include <cuda_runtime.h>

// ----------------------------------------------------------------------------
// NeighborAttention, 3-kernel pipeline:
//   qk_kernel : Qt[n,h,:] = (1/sqrt(32)) * (hV[n] @ WQ^T)_h @ WK_h   (fused)
//   attn      : masked softmax attention over neighbors -> ctx[n, h*128+a]
//   vo_kernel : out = (ctx_h @ WV_h^T) @ WO^T                         (fused)
// Removes Q and vout intermediates; 3 launches instead of 5.
// ----------------------------------------------------------------------------

#define MAXN 30720
#define HDIM 128
#define KNB 32

__device__ float g_Qt[MAXN * 512];
__device__ float g_ctx[MAXN * 512];

// ----------------------------------------------------------------------------
// Fused QK projection. One block = 128 nodes, 256 threads.
//   Phase 1: Q[128,128] = hV_tile @ WQ^T   (K=128) -> smem Qs (row-major)
//   Phase 2: per head h: Qt[:,h*128+b] = Q[:,32h:32h+32] @ WK_h  (K=32)
// smem: As[16][132] + Bs[16][132] + B2[32][132] + Qs[128][132] = 101376 B
// ----------------------------------------------------------------------------
__global__ void __launch_bounds__(256) qk_kernel(
    const float* __restrict__ hV, const float* __restrict__ WQ,
    const float* __restrict__ WK, float* __restrict__ Qt, int N)
{
    extern __shared__ float sm[];
    float* As = sm;            // [16][132]
    float* Bs = sm + 2112;     // [16][132]
    float* B2 = sm + 4224;     // [32][132]
    float* Qs = sm + 8448;     // [128][132]

    const int t  = threadIdx.x;
    const int m0 = blockIdx.x * 128;
    const int tm = t >> 4;     // 0..15
    const int tn = t & 15;     // 0..15

    // ---------------- phase 1: Q = hV @ WQ^T ----------------
    float acc[8][8];
    #pragma unroll
    for (int i = 0; i < 8; i++)
        #pragma unroll
        for (int j = 0; j < 8; j++) acc[i][j] = 0.f;

    for (int k0 = 0; k0 < 128; k0 += 16) {
        // As[k][r] = hV[m0+r][k0+k]
        #pragma unroll
        for (int i = 0; i < 2; i++) {
            int idx4 = t + 256 * i;          // 0..511
            int r  = idx4 >> 2;              // 0..127
            int kc = (idx4 & 3) << 2;        // 0,4,8,12
            float4 v = make_float4(0.f, 0.f, 0.f, 0.f);
            if (m0 + r < N) v = *(const float4*)&hV[(long long)(m0 + r) * 128 + k0 + kc];
            As[(kc + 0) * 132 + r] = v.x;
            As[(kc + 1) * 132 + r] = v.y;
            As[(kc + 2) * 132 + r] = v.z;
            As[(kc + 3) * 132 + r] = v.w;
        }
        // Bs[k][j] = WQ[j][k0+k]
        #pragma unroll
        for (int i = 0; i < 2; i++) {
            int idx4 = t + 256 * i;
            int j  = idx4 >> 2;
            int kc = (idx4 & 3) << 2;
            float4 v = *(const float4*)&WQ[j * 128 + k0 + kc];
            Bs[(kc + 0) * 132 + j] = v.x;
            Bs[(kc + 1) * 132 + j] = v.y;
            Bs[(kc + 2) * 132 + j] = v.z;
            Bs[(kc + 3) * 132 + j] = v.w;
        }
        __syncthreads();

        #pragma unroll
        for (int kk = 0; kk < 16; kk++) {
            float a[8], b[8];
            float4 a0 = *(const float4*)&As[kk * 132 + tm * 4];
            float4 a1 = *(const float4*)&As[kk * 132 + tm * 4 + 64];
            a[0]=a0.x; a[1]=a0.y; a[2]=a0.z; a[3]=a0.w;
            a[4]=a1.x; a[5]=a1.y; a[6]=a1.z; a[7]=a1.w;
            float4 b0 = *(const float4*)&Bs[kk * 132 + tn * 4];
            float4 b1 = *(const float4*)&Bs[kk * 132 + tn * 4 + 64];
            b[0]=b0.x; b[1]=b0.y; b[2]=b0.z; b[3]=b0.w;
            b[4]=b1.x; b[5]=b1.y; b[6]=b1.z; b[7]=b1.w;
            #pragma unroll
            for (int i = 0; i < 8; i++)
                #pragma unroll
                for (int j = 0; j < 8; j++)
                    acc[i][j] += a[i] * b[j];
        }
        __syncthreads();
    }

    // Q -> smem, row-major Qs[r][c]
    #pragma unroll
    for (int i = 0; i < 8; i++) {
        int r = tm * 4 + (i >> 2) * 64 + (i & 3);
        float4 v0 = make_float4(acc[i][0], acc[i][1], acc[i][2], acc[i][3]);
        float4 v1 = make_float4(acc[i][4], acc[i][5], acc[i][6], acc[i][7]);
        *(float4*)&Qs[r * 132 + tn * 4]      = v0;
        *(float4*)&Qs[r * 132 + tn * 4 + 64] = v1;
    }
    __syncthreads();

    // ---------------- phase 2: per-head Qt = Q_h @ WK_h ----------------
    const float scale = 0.17677669529663687f;  // 1/sqrt(32)
    for (int h = 0; h < 4; h++) {
        // B2[m][b] = WK[32h+m][b]
        #pragma unroll
        for (int i = 0; i < 4; i++) {
            int idx4 = t + 256 * i;          // 0..1023
            int m  = idx4 >> 5;              // 0..31
            int bc = (idx4 & 31) << 2;       // 0..124
            float4 v = *(const float4*)&WK[(32 * h + m) * 128 + bc];
            *(float4*)&B2[m * 132 + bc] = v;
        }
        __syncthreads();

        float acc2[8][8];
        #pragma unroll
        for (int i = 0; i < 8; i++)
            #pragma unroll
            for (int j = 0; j < 8; j++) acc2[i][j] = 0.f;

        #pragma unroll
        for (int kk = 0; kk < 32; kk++) {
            float a[8], b[8];
            #pragma unroll
            for (int i = 0; i < 8; i++) {
                int r = tm * 4 + (i >> 2) * 64 + (i & 3);
                a[i] = Qs[r * 132 + h * 32 + kk];      // warp-broadcast
            }
            float4 b0 = *(const float4*)&B2[kk * 132 + tn * 4];
            float4 b1 = *(const float4*)&B2[kk * 132 + tn * 4 + 64];
            b[0]=b0.x; b[1]=b0.y; b[2]=b0.z; b[3]=b0.w;
            b[4]=b1.x; b[5]=b1.y; b[6]=b1.z; b[7]=b1.w;
            #pragma unroll
            for (int i = 0; i < 8; i++)
                #pragma unroll
                for (int j = 0; j < 8; j++)
                    acc2[i][j] += a[i] * b[j];
        }

        #pragma unroll
        for (int i = 0; i < 8; i++) {
            int r = tm * 4 + (i >> 2) * 64 + (i & 3);
            if (m0 + r < N) {
                float4 v0 = make_float4(acc2[i][0]*scale, acc2[i][1]*scale,
                                        acc2[i][2]*scale, acc2[i][3]*scale);
                float4 v1 = make_float4(acc2[i][4]*scale, acc2[i][5]*scale,
                                        acc2[i][6]*scale, acc2[i][7]*scale);
                float* qp = &Qt[(long long)(m0 + r) * 512 + h * 128];
                *(float4*)&qp[tn * 4]      = v0;
                *(float4*)&qp[tn * 4 + 64] = v1;
            }
        }
        __syncthreads();
    }
}

// ----------------------------------------------------------------------------
// Fused VO projection. One block = 128 nodes, 256 threads.
//   Phase 1: per head: vout[:,32h+m] = ctx_h @ WV_h^T (K=128) -> smem Vs
//   Phase 2: out = vout @ WO^T (K=128)
// smem: As[16][132] + Bs[16][132] + Vs[128][132] = 84480 B
// ----------------------------------------------------------------------------
__global__ void __launch_bounds__(256) vo_kernel(
    const float* __restrict__ ctx, const float* __restrict__ WV,
    const float* __restrict__ WO, float* __restrict__ out, int N)
{
    extern __shared__ float sm[];
    float* As = sm;            // [16][132]
    float* Bs = sm + 2112;     // [16][132]
    float* Vs = sm + 4224;     // [128][132]

    const int t  = threadIdx.x;
    const int m0 = blockIdx.x * 128;

    // ---------------- phase 1: vout per head ----------------
    {
        const int tm = t >> 3;   // 0..31
        const int tn = t & 7;    // 0..7
        for (int h = 0; h < 4; h++) {
            float acc[4][4];
            #pragma unroll
            for (int i = 0; i < 4; i++)
                #pragma unroll
                for (int j = 0; j < 4; j++) acc[i][j] = 0.f;

            for (int k0 = 0; k0 < 128; k0 += 16) {
                // As[k][r] = ctx[m0+r][128h + k0+k]
                #pragma unroll
                for (int i = 0; i < 2; i++) {
                    int idx4 = t + 256 * i;
                    int r  = idx4 >> 2;
                    int kc = (idx4 & 3) << 2;
                    float4 v = make_float4(0.f, 0.f, 0.f, 0.f);
                    if (m0 + r < N)
                        v = *(const float4*)&ctx[(long long)(m0 + r) * 512 + h * 128 + k0 + kc];
                    As[(kc + 0) * 132 + r] = v.x;
                    As[(kc + 1) * 132 + r] = v.y;
                    As[(kc + 2) * 132 + r] = v.z;
                    As[(kc + 3) * 132 + r] = v.w;
                }
                // Bs[k][m] = WV[32h+m][k0+k]  (only 32 cols)
                if (t < 128) {
                    int m  = t >> 2;
                    int kc = (t & 3) << 2;
                    float4 v = *(const float4*)&WV[(32 * h + m) * 128 + k0 + kc];
                    Bs[(kc + 0) * 132 + m] = v.x;
                    Bs[(kc + 1) * 132 + m] = v.y;
                    Bs[(kc + 2) * 132 + m] = v.z;
                    Bs[(kc + 3) * 132 + m] = v.w;
                }
                __syncthreads();

                #pragma unroll
                for (int kk = 0; kk < 16; kk++) {
                    float4 a4 = *(const float4*)&As[kk * 132 + tm * 4];
                    float4 b4 = *(const float4*)&Bs[kk * 132 + tn * 4];
                    float a[4] = {a4.x, a4.y, a4.z, a4.w};
                    float b[4] = {b4.x, b4.y, b4.z, b4.w};
                    #pragma unroll
                    for (int i = 0; i < 4; i++)
                        #pragma unroll
                        for (int j = 0; j < 4; j++)
                            acc[i][j] += a[i] * b[j];
                }
                __syncthreads();
            }
            // vout -> Vs[r][32h + c]
            #pragma unroll
            for (int i = 0; i < 4; i++) {
                int r = tm * 4 + i;
                float4 v = make_float4(acc[i][0], acc[i][1], acc[i][2], acc[i][3]);
                *(float4*)&Vs[r * 132 + 32 * h + tn * 4] = v;
            }
        }
    }
    __syncthreads();

    // ---------------- phase 2: out = vout @ WO^T ----------------
    {
        const int tm = t >> 4;   // 0..15
        const int tn = t & 15;   // 0..15
        float acc2[8][8];
        #pragma unroll
        for (int i = 0; i < 8; i++)
            #pragma unroll
            for (int j = 0; j < 8; j++) acc2[i][j] = 0.f;

        for (int k0 = 0; k0 < 128; k0 += 16) {
            // Bs[k][j] = WO[j][k0+k]
            #pragma unroll
            for (int i = 0; i < 2; i++) {
                int idx4 = t + 256 * i;
                int j  = idx4 >> 2;
                int kc = (idx4 & 3) << 2;
                float4 v = *(const float4*)&WO[j * 128 + k0 + kc];
                Bs[(kc + 0) * 132 + j] = v.x;
                Bs[(kc + 1) * 132 + j] = v.y;
                Bs[(kc + 2) * 132 + j] = v.z;
                Bs[(kc + 3) * 132 + j] = v.w;
            }
            __syncthreads();

            #pragma unroll
            for (int kk = 0; kk < 16; kk++) {
                float a[8], b[8];
                #pragma unroll
                for (int i = 0; i < 8; i++) {
                    int r = tm * 4 + (i >> 2) * 64 + (i & 3);
                    a[i] = Vs[r * 132 + k0 + kk];     // warp-broadcast
                }
                float4 b0 = *(const float4*)&Bs[kk * 132 + tn * 4];
                float4 b1 = *(const float4*)&Bs[kk * 132 + tn * 4 + 64];
                b[0]=b0.x; b[1]=b0.y; b[2]=b0.z; b[3]=b0.w;
                b[4]=b1.x; b[5]=b1.y; b[6]=b1.z; b[7]=b1.w;
                #pragma unroll
                for (int i = 0; i < 8; i++)
                    #pragma unroll
                    for (int j = 0; j < 8; j++)
                        acc2[i][j] += a[i] * b[j];
            }
            __syncthreads();
        }

        #pragma unroll
        for (int i = 0; i < 8; i++) {
            int r = tm * 4 + (i >> 2) * 64 + (i & 3);
            if (m0 + r < N) {
                float4 v0 = make_float4(acc2[i][0], acc2[i][1], acc2[i][2], acc2[i][3]);
                float4 v1 = make_float4(acc2[i][4], acc2[i][5], acc2[i][6], acc2[i][7]);
                float* op = &out[(long long)(m0 + r) * 128];
                *(float4*)&op[tn * 4]      = v0;
                *(float4*)&op[tn * 4 + 64] = v1;
            }
        }
    }
}

// ----------------------------------------------------------------------------
// Fused neighbor attention, one block (128 threads) per node.
// Masked-out neighbor rows of h_E are never loaded from DRAM.
// ----------------------------------------------------------------------------
__global__ void __launch_bounds__(128) attn_kernel(
    const float* __restrict__ hE, const int* __restrict__ mask,
    const float* __restrict__ Qt, float* __restrict__ ctx)
{
    __shared__ float Es[32 * 132];
    __shared__ float Qts[4 * 132];
    __shared__ float Lp[512];
    __shared__ float Asm[128];
    __shared__ int   msk[32];

    const int n = blockIdx.x;
    const int t = threadIdx.x;

    if (t < 32) msk[t] = mask[(long long)n * KNB + t];
    {
        const float* q = Qt + (long long)n * 512;
        int h  = t >> 5;
        int a4 = t & 31;
        *(float4*)&Qts[h * 132 + (a4 << 2)] = *(const float4*)&q[t << 2];
    }
    __syncthreads();

    const float* e = hE + (long long)n * (KNB * HDIM);
    #pragma unroll
    for (int i = 0; i < 8; i++) {
        int idx4 = t + 128 * i;
        int k  = idx4 >> 5;
        int a4 = idx4 & 31;
        float4 v = make_float4(0.f, 0.f, 0.f, 0.f);
        if (msk[k]) v = *(const float4*)&e[idx4 << 2];
        *(float4*)&Es[k * 132 + (a4 << 2)] = v;
    }
    __syncthreads();

    {
        const int ac = t >> 5;
        const int k  = t & 31;
        const float* ep = &Es[k * 132 + (ac << 5)];
        float p0 = 0.f, p1 = 0.f, p2 = 0.f, p3 = 0.f;
        #pragma unroll
        for (int s = 0; s < 8; s++) {
            float4 e4 = *(const float4*)&ep[s << 2];
            int ao = (ac << 5) + (s << 2);
            float4 q0 = *(const float4*)&Qts[0 * 132 + ao];
            float4 q1 = *(const float4*)&Qts[1 * 132 + ao];
            float4 q2 = *(const float4*)&Qts[2 * 132 + ao];
            float4 q3 = *(const float4*)&Qts[3 * 132 + ao];
            p0 += q0.x * e4.x + q0.y * e4.y + q0.z * e4.z + q0.w * e4.w;
            p1 += q1.x * e4.x + q1.y * e4.y + q1.z * e4.z + q1.w * e4.w;
            p2 += q2.x * e4.x + q2.y * e4.y + q2.z * e4.z + q2.w * e4.w;
            p3 += q3.x * e4.x + q3.y * e4.y + q3.z * e4.z + q3.w * e4.w;
        }
        Lp[(ac << 7) + 0 * 32 + k] = p0;
        Lp[(ac << 7) + 1 * 32 + k] = p1;
        Lp[(ac << 7) + 2 * 32 + k] = p2;
        Lp[(ac << 7) + 3 * 32 + k] = p3;
    }
    __syncthreads();

    {
        const int h = t >> 5, k = t & 31;
        float x = Lp[0 * 128 + h * 32 + k] + Lp[1 * 128 + h * 32 + k]
                + Lp[2 * 128 + h * 32 + k] + Lp[3 * 128 + h * 32 + k];
        bool mv  = (msk[k] != 0);
        float xm = mv ? x : -3.402823466e+38f;
        float mx = xm;
        #pragma unroll
        for (int o = 16; o > 0; o >>= 1) mx = fmaxf(mx, __shfl_xor_sync(0xffffffffu, mx, o));
        float p = mv ? __expf(xm - mx) : 0.f;
        float sm = p;
        #pragma unroll
        for (int o = 16; o > 0; o >>= 1) sm += __shfl_xor_sync(0xffffffffu, sm, o);
        float inv = (sm > 0.f) ? (1.f / sm) : 0.f;
        Asm[h * 32 + k] = p * inv;
    }
    __syncthreads();

    {
        float c0 = 0.f, c1 = 0.f, c2 = 0.f, c3 = 0.f;
        #pragma unroll
        for (int k4 = 0; k4 < 8; k4++) {
            float4 a0 = *(const float4*)&Asm[0 * 32 + (k4 << 2)];
            float4 a1 = *(const float4*)&Asm[1 * 32 + (k4 << 2)];
            float4 a2 = *(const float4*)&Asm[2 * 32 + (k4 << 2)];
            float4 a3 = *(const float4*)&Asm[3 * 32 + (k4 << 2)];
            float w0[4] = {a0.x, a0.y, a0.z, a0.w};
            float w1[4] = {a1.x, a1.y, a1.z, a1.w};
            float w2[4] = {a2.x, a2.y, a2.z, a2.w};
            float w3[4] = {a3.x, a3.y, a3.z, a3.w};
            #pragma unroll
            for (int i = 0; i < 4; i++) {
                float ev = Es[((k4 << 2) + i) * 132 + t];
                c0 += w0[i] * ev;
                c1 += w1[i] * ev;
                c2 += w2[i] * ev;
                c3 += w3[i] * ev;
            }
        }
        float* cp = ctx + (long long)n * 512 + t;
        cp[0]   = c0;
        cp[128] = c1;
        cp[256] = c2;
        cp[384] = c3;
    }
}

// ----------------------------------------------------------------------------
extern "C" void kernel_launch(void* const* d_in, const int* in_sizes, int n_in,
                              void* d_out, int out_size)
{
    const float* hV   = (const float*)d_in[0];
    const float* hE   = (const float*)d_in[1];
    const int*   mask = (const int*)  d_in[2];
    const float* WQ   = (const float*)d_in[3];
    const float* WK   = (const float*)d_in[4];
    const float* WV   = (const float*)d_in[5];
    const float* WO   = (const float*)d_in[6];
    float*       out  = (float*)d_out;

    const int N = in_sizes[0] / HDIM;
    if (N <= 0) return;

    float *Qt, *Ctx;
    cudaGetSymbolAddress((void**)&Qt,  g_Qt);
    cudaGetSymbolAddress((void**)&Ctx, g_ctx);

    const int QK_SMEM = 101376;
    const int VO_SMEM = 84480;
    cudaFuncSetAttribute(qk_kernel, cudaFuncAttributeMaxDynamicSharedMemorySize, QK_SMEM);
    cudaFuncSetAttribute(vo_kernel, cudaFuncAttributeMaxDynamicSharedMemorySize, VO_SMEM);

    const int MB = (N + 127) / 128;

    qk_kernel<<<MB, 256, QK_SMEM>>>(hV, WQ, WK, Qt, N);
    attn_kernel<<<N, 128>>>(hE, mask, Qt, Ctx);
    vo_kernel<<<MB, 256, VO_SMEM>>>(Ctx, WV, WO, out, N);
}

// round 9
// speedup vs baseline: 1.1752x; 1.1752x over previous
#include <cuda_runtime.h>

// ----------------------------------------------------------------------------
// NeighborAttention, restructured (63 GFLOP -> 3.9 GFLOP), 5 launches:
//   1) Q   = hV @ WQ^T
//   2) Qt  = (1/sqrt(32)) * Q_h @ WK_h          (per head)
//   3) attn: persistent, software-pipelined     -> ctx
//   4) vout = ctx_h @ WV_h^T                    (per head)
//   5) out  = vout @ WO^T
// ----------------------------------------------------------------------------

#define MAXN 30720
#define HDIM 128
#define KNB 32

__device__ float g_Q[MAXN * 128];
__device__ float g_Qt[MAXN * 512];
__device__ float g_ctx[MAXN * 512];
__device__ float g_vout[MAXN * 128];

// ----------------------------------------------------------------------------
// Tiled SGEMM, 8x8 / 8x4 register microtiles.
// ----------------------------------------------------------------------------
template <int BM, int BN, int BK, int TM, int TN, bool TRANSB>
__global__ void __launch_bounds__((BM / TM) * (BN / TN)) sgemm_kernel(
    const float* __restrict__ A, const float* __restrict__ B, float* __restrict__ C,
    int M, int Nc, int K, int lda, int ldb, int ldc,
    long long aB, long long bB, long long cB, float alpha)
{
    constexpr int NT = (BM / TM) * (BN / TN);
    __shared__ float As[BK][BM + 4];
    __shared__ float Bs[BK][BN + 4];

    const long long bz = blockIdx.z;
    A += bz * aB; B += bz * bB; C += bz * cB;

    const int m0 = blockIdx.y * BM;
    const int n0 = blockIdx.x * BN;
    const int t  = threadIdx.x;
    const int tm = t / (BN / TN);
    const int tn = t % (BN / TN);

    float acc[TM][TN] = {};

    for (int k0 = 0; k0 < K; k0 += BK) {
        constexpr int A4 = (BM * BK) / (4 * NT);
        #pragma unroll
        for (int i = 0; i < A4; i++) {
            int idx4 = t + NT * i;
            int r  = idx4 / (BK / 4);
            int kc = (idx4 % (BK / 4)) * 4;
            float4 v = make_float4(0.f, 0.f, 0.f, 0.f);
            int gr = m0 + r;
            if (gr < M) v = *(const float4*)&A[(long long)gr * lda + k0 + kc];
            As[kc + 0][r] = v.x;
            As[kc + 1][r] = v.y;
            As[kc + 2][r] = v.z;
            As[kc + 3][r] = v.w;
        }
        if (!TRANSB) {
            constexpr int B4 = (BK * BN) / (4 * NT);
            #pragma unroll
            for (int i = 0; i < B4; i++) {
                int idx4 = t + NT * i;
                int kr = idx4 / (BN / 4);
                int nc = (idx4 % (BN / 4)) * 4;
                float4 v = make_float4(0.f, 0.f, 0.f, 0.f);
                if (n0 + nc < Nc) v = *(const float4*)&B[(long long)(k0 + kr) * ldb + n0 + nc];
                *(float4*)&Bs[kr][nc] = v;
            }
        } else {
            constexpr int B4 = (BN * BK) / (4 * NT);
            #pragma unroll
            for (int i = 0; i < B4; i++) {
                int idx4 = t + NT * i;
                int n  = idx4 / (BK / 4);
                int kc = (idx4 % (BK / 4)) * 4;
                float4 v = make_float4(0.f, 0.f, 0.f, 0.f);
                if (n0 + n < Nc) v = *(const float4*)&B[(long long)(n0 + n) * ldb + k0 + kc];
                Bs[kc + 0][n] = v.x;
                Bs[kc + 1][n] = v.y;
                Bs[kc + 2][n] = v.z;
                Bs[kc + 3][n] = v.w;
            }
        }
        __syncthreads();

        #pragma unroll
        for (int kk = 0; kk < BK; kk++) {
            float a[TM], b[TN];
            #pragma unroll
            for (int h = 0; h < TM / 4; h++) {
                float4 v = *(const float4*)&As[kk][tm * 4 + h * (BM / 2)];
                a[h * 4 + 0] = v.x; a[h * 4 + 1] = v.y;
                a[h * 4 + 2] = v.z; a[h * 4 + 3] = v.w;
            }
            #pragma unroll
            for (int h = 0; h < TN / 4; h++) {
                float4 v = *(const float4*)&Bs[kk][tn * 4 + h * (BN / 2)];
                b[h * 4 + 0] = v.x; b[h * 4 + 1] = v.y;
                b[h * 4 + 2] = v.z; b[h * 4 + 3] = v.w;
            }
            #pragma unroll
            for (int i = 0; i < TM; i++)
                #pragma unroll
                for (int j = 0; j < TN; j++)
                    acc[i][j] += a[i] * b[j];
        }
        __syncthreads();
    }

    #pragma unroll
    for (int i = 0; i < TM; i++) {
        int r = m0 + tm * 4 + (i / 4) * (BM / 2) + (i % 4);
        if (r >= M) continue;
        #pragma unroll
        for (int jh = 0; jh < TN / 4; jh++) {
            int c = n0 + tn * 4 + jh * (BN / 2);
            if (c < Nc) {
                float4 v = make_float4(acc[i][jh * 4 + 0] * alpha, acc[i][jh * 4 + 1] * alpha,
                                       acc[i][jh * 4 + 2] * alpha, acc[i][jh * 4 + 3] * alpha);
                *(float4*)&C[(long long)r * ldc + c] = v;
            }
        }
    }
}

// ----------------------------------------------------------------------------
// Persistent fused neighbor attention. Grid-stride over nodes; each iteration
// prefetches the NEXT node's E tile (mask-predicated) + Qt into registers,
// computes the CURRENT node from smem, then commits the prefetch. Mask ring
// (depth 3) keeps the predicate resident in smem two iterations ahead.
// ----------------------------------------------------------------------------
__global__ void __launch_bounds__(128) attn_kernel(
    const float* __restrict__ hE, const int* __restrict__ mask,
    const float* __restrict__ Qt, float* __restrict__ ctx, int N)
{
    __shared__ float Es[32 * 132];
    __shared__ float Qts[4 * 132];
    __shared__ float Lp[512];
    __shared__ float Asm[128];
    __shared__ int   msk[3][32];

    const int t  = threadIdx.x;
    const int G  = gridDim.x;
    const int n0 = blockIdx.x;
    if (n0 >= N) return;

    // --- prologue: masks for iterations 0 and 1 ---
    if (t < 32) {
        msk[0][t] = mask[(long long)n0 * KNB + t];
        long long n1 = n0 + (long long)G;
        msk[1][t] = (n1 < N) ? mask[n1 * KNB + t] : 0;
    }
    __syncthreads();

    float4 ereg[8];
    float4 qreg;

    // --- prefetch node n0 and commit to smem ---
    {
        const float* e = hE + (long long)n0 * (KNB * HDIM);
        #pragma unroll
        for (int ii = 0; ii < 8; ii++) {
            int idx4 = t + 128 * ii;
            int k = idx4 >> 5;                       // warp-uniform
            ereg[ii] = make_float4(0.f, 0.f, 0.f, 0.f);
            if (msk[0][k]) ereg[ii] = *(const float4*)&e[idx4 << 2];
        }
        qreg = *(const float4*)&Qt[(long long)n0 * 512 + t * 4];
        #pragma unroll
        for (int ii = 0; ii < 8; ii++) {
            int idx4 = t + 128 * ii;
            int k = idx4 >> 5, a4 = idx4 & 31;
            *(float4*)&Es[k * 132 + (a4 << 2)] = ereg[ii];
        }
        int h = t >> 5, a4 = t & 31;
        *(float4*)&Qts[h * 132 + (a4 << 2)] = qreg;
    }
    __syncthreads();

    for (int i = 0; ; i++) {
        const long long n  = n0 + (long long)i * G;
        const long long nn = n + G;
        const bool has_next = (nn < N);
        int mreg = 0;

        // --- phase A: issue prefetch for node nn (results land in regs) ---
        if (has_next) {
            const int s1 = (i + 1) % 3;
            const float* e = hE + nn * (KNB * HDIM);
            #pragma unroll
            for (int ii = 0; ii < 8; ii++) {
                int idx4 = t + 128 * ii;
                int k = idx4 >> 5;                   // warp-uniform
                ereg[ii] = make_float4(0.f, 0.f, 0.f, 0.f);
                if (msk[s1][k]) ereg[ii] = *(const float4*)&e[idx4 << 2];
            }
            qreg = *(const float4*)&Qt[nn * 512 + t * 4];
            if (t < 32) {
                long long n2 = n + 2LL * G;
                mreg = (n2 < N) ? mask[n2 * KNB + t] : 0;
            }
        }

        // --- phase B: compute node n from smem ---
        const int* mc = msk[i % 3];

        {   // logits partials: warp = a-chunk, lane = k
            const int ac = t >> 5;
            const int k  = t & 31;
            const float* ep = &Es[k * 132 + (ac << 5)];
            float p0 = 0.f, p1 = 0.f, p2 = 0.f, p3 = 0.f;
            #pragma unroll
            for (int s = 0; s < 8; s++) {
                float4 e4 = *(const float4*)&ep[s << 2];
                int ao = (ac << 5) + (s << 2);
                float4 q0 = *(const float4*)&Qts[0 * 132 + ao];   // broadcast
                float4 q1 = *(const float4*)&Qts[1 * 132 + ao];
                float4 q2 = *(const float4*)&Qts[2 * 132 + ao];
                float4 q3 = *(const float4*)&Qts[3 * 132 + ao];
                p0 += q0.x * e4.x + q0.y * e4.y + q0.z * e4.z + q0.w * e4.w;
                p1 += q1.x * e4.x + q1.y * e4.y + q1.z * e4.z + q1.w * e4.w;
                p2 += q2.x * e4.x + q2.y * e4.y + q2.z * e4.z + q2.w * e4.w;
                p3 += q3.x * e4.x + q3.y * e4.y + q3.z * e4.z + q3.w * e4.w;
            }
            Lp[(ac << 7) + 0 * 32 + k] = p0;
            Lp[(ac << 7) + 1 * 32 + k] = p1;
            Lp[(ac << 7) + 2 * 32 + k] = p2;
            Lp[(ac << 7) + 3 * 32 + k] = p3;
        }
        __syncthreads();

        {   // masked softmax: warp = head, lane = k
            const int h = t >> 5, k = t & 31;
            float x = Lp[0 * 128 + h * 32 + k] + Lp[1 * 128 + h * 32 + k]
                    + Lp[2 * 128 + h * 32 + k] + Lp[3 * 128 + h * 32 + k];
            bool mv  = (mc[k] != 0);
            float xm = mv ? x : -3.402823466e+38f;
            float mx = xm;
            #pragma unroll
            for (int o = 16; o > 0; o >>= 1) mx = fmaxf(mx, __shfl_xor_sync(0xffffffffu, mx, o));
            float p = mv ? __expf(xm - mx) : 0.f;
            float sm = p;
            #pragma unroll
            for (int o = 16; o > 0; o >>= 1) sm += __shfl_xor_sync(0xffffffffu, sm, o);
            float inv = (sm > 0.f) ? (1.f / sm) : 0.f;
            Asm[h * 32 + k] = p * inv;
        }
        __syncthreads();

        {   // ctx: thread t owns column a = t
            float c0 = 0.f, c1 = 0.f, c2 = 0.f, c3 = 0.f;
            #pragma unroll
            for (int k4 = 0; k4 < 8; k4++) {
                float4 a0 = *(const float4*)&Asm[0 * 32 + (k4 << 2)];
                float4 a1 = *(const float4*)&Asm[1 * 32 + (k4 << 2)];
                float4 a2 = *(const float4*)&Asm[2 * 32 + (k4 << 2)];
                float4 a3 = *(const float4*)&Asm[3 * 32 + (k4 << 2)];
                float w0[4] = {a0.x, a0.y, a0.z, a0.w};
                float w1[4] = {a1.x, a1.y, a1.z, a1.w};
                float w2[4] = {a2.x, a2.y, a2.z, a2.w};
                float w3[4] = {a3.x, a3.y, a3.z, a3.w};
                #pragma unroll
                for (int ii = 0; ii < 4; ii++) {
                    float ev = Es[((k4 << 2) + ii) * 132 + t];
                    c0 += w0[ii] * ev;
                    c1 += w1[ii] * ev;
                    c2 += w2[ii] * ev;
                    c3 += w3[ii] * ev;
                }
            }
            float* cp = ctx + n * 512 + t;
            cp[0]   = c0;
            cp[128] = c1;
            cp[256] = c2;
            cp[384] = c3;
        }

        if (!has_next) break;

        // --- phase C: commit prefetched tile ---
        __syncthreads();
        #pragma unroll
        for (int ii = 0; ii < 8; ii++) {
            int idx4 = t + 128 * ii;
            int k = idx4 >> 5, a4 = idx4 & 31;
            *(float4*)&Es[k * 132 + (a4 << 2)] = ereg[ii];
        }
        {
            int h = t >> 5, a4 = t & 31;
            *(float4*)&Qts[h * 132 + (a4 << 2)] = qreg;
        }
        if (t < 32) msk[(i + 2) % 3][t] = mreg;
        __syncthreads();
    }
}

// ----------------------------------------------------------------------------
extern "C" void kernel_launch(void* const* d_in, const int* in_sizes, int n_in,
                              void* d_out, int out_size)
{
    const float* hV   = (const float*)d_in[0];
    const float* hE   = (const float*)d_in[1];
    const int*   mask = (const int*)  d_in[2];
    const float* WQ   = (const float*)d_in[3];
    const float* WK   = (const float*)d_in[4];
    const float* WV   = (const float*)d_in[5];
    const float* WO   = (const float*)d_in[6];
    float*       out  = (float*)d_out;

    const int N = in_sizes[0] / HDIM;
    if (N <= 0) return;

    float *Q, *Qt, *Ctx, *Vout;
    cudaGetSymbolAddress((void**)&Q,    g_Q);
    cudaGetSymbolAddress((void**)&Qt,   g_Qt);
    cudaGetSymbolAddress((void**)&Ctx,  g_ctx);
    cudaGetSymbolAddress((void**)&Vout, g_vout);

    const int MB64  = (N + 63) / 64;
    const int MB128 = (N + 127) / 128;
    const float inv_sqrt_d = 0.17677669529663687f;  // 1/sqrt(32)

    // 1) Q = h_V @ W_Q^T
    sgemm_kernel<64, 128, 16, 8, 8, true><<<dim3(1, MB64, 1), 128>>>(
        hV, WQ, Q, N, 128, 128, 128, 128, 128, 0, 0, 0, 1.f);

    // 2) Qt[n, h*128+b] = (1/sqrt(d)) * Q[n,32h:32h+32] @ W_K[32h:32h+32,:]
    sgemm_kernel<64, 128, 16, 8, 8, false><<<dim3(1, MB64, 4), 128>>>(
        Q, WK, Qt, N, 128, 32, 128, 128, 512,
        /*aB=*/32, /*bB=*/32 * 128, /*cB=*/128, inv_sqrt_d);

    // 3) persistent fused attention -> ctx[N,512]
    int attn_grid = 888;
    if (attn_grid > N) attn_grid = N;
    attn_kernel<<<attn_grid, 128>>>(hE, mask, Qt, Ctx, N);

    // 4) vout[n, 32h+j] = ctx[n, 128h:] @ W_V[32h+j,:]
    sgemm_kernel<128, 32, 16, 8, 4, true><<<dim3(1, MB128, 4), 128>>>(
        Ctx, WV, Vout, N, 32, 128, 512, 128, 128,
        /*aB=*/128, /*bB=*/32 * 128, /*cB=*/32, 1.f);

    // 5) out = vout @ W_O^T
    sgemm_kernel<64, 128, 16, 8, 8, true><<<dim3(1, MB64, 1), 128>>>(
        Vout, WO, out, N, 128, 128, 128, 128, 128, 0, 0, 0, 1.f);
}

// round 10
// speedup vs baseline: 1.1818x; 1.0056x over previous
#include <cuda_runtime.h>

// ----------------------------------------------------------------------------
// NeighborAttention, restructured (63 GFLOP -> 3.9 GFLOP), 5 launches:
//   1) Q   = hV @ WQ^T
//   2) Qt  = (1/sqrt(32)) * Q_h @ WK_h          (per head)
//   3) attn: persistent, software-pipelined     -> ctx
//   4) vout = ctx_h @ WV_h^T                    (per head)
//   5) out  = vout @ WO^T
// ----------------------------------------------------------------------------

#define MAXN 30720
#define HDIM 128
#define KNB 32

__device__ float g_Q[MAXN * 128];
__device__ float g_Qt[MAXN * 512];
__device__ float g_ctx[MAXN * 512];
__device__ float g_vout[MAXN * 128];

// ----------------------------------------------------------------------------
// Tiled SGEMM, 8x8 / 8x4 register microtiles.
// ----------------------------------------------------------------------------
template <int BM, int BN, int BK, int TM, int TN, bool TRANSB>
__global__ void __launch_bounds__((BM / TM) * (BN / TN)) sgemm_kernel(
    const float* __restrict__ A, const float* __restrict__ B, float* __restrict__ C,
    int M, int Nc, int K, int lda, int ldb, int ldc,
    long long aB, long long bB, long long cB, float alpha)
{
    constexpr int NT = (BM / TM) * (BN / TN);
    __shared__ float As[BK][BM + 4];
    __shared__ float Bs[BK][BN + 4];

    const long long bz = blockIdx.z;
    A += bz * aB; B += bz * bB; C += bz * cB;

    const int m0 = blockIdx.y * BM;
    const int n0 = blockIdx.x * BN;
    const int t  = threadIdx.x;
    const int tm = t / (BN / TN);
    const int tn = t % (BN / TN);

    float acc[TM][TN] = {};

    for (int k0 = 0; k0 < K; k0 += BK) {
        constexpr int A4 = (BM * BK) / (4 * NT);
        #pragma unroll
        for (int i = 0; i < A4; i++) {
            int idx4 = t + NT * i;
            int r  = idx4 / (BK / 4);
            int kc = (idx4 % (BK / 4)) * 4;
            float4 v = make_float4(0.f, 0.f, 0.f, 0.f);
            int gr = m0 + r;
            if (gr < M) v = *(const float4*)&A[(long long)gr * lda + k0 + kc];
            As[kc + 0][r] = v.x;
            As[kc + 1][r] = v.y;
            As[kc + 2][r] = v.z;
            As[kc + 3][r] = v.w;
        }
        if (!TRANSB) {
            constexpr int B4 = (BK * BN) / (4 * NT);
            #pragma unroll
            for (int i = 0; i < B4; i++) {
                int idx4 = t + NT * i;
                int kr = idx4 / (BN / 4);
                int nc = (idx4 % (BN / 4)) * 4;
                float4 v = make_float4(0.f, 0.f, 0.f, 0.f);
                if (n0 + nc < Nc) v = *(const float4*)&B[(long long)(k0 + kr) * ldb + n0 + nc];
                *(float4*)&Bs[kr][nc] = v;
            }
        } else {
            constexpr int B4 = (BN * BK) / (4 * NT);
            #pragma unroll
            for (int i = 0; i < B4; i++) {
                int idx4 = t + NT * i;
                int n  = idx4 / (BK / 4);
                int kc = (idx4 % (BK / 4)) * 4;
                float4 v = make_float4(0.f, 0.f, 0.f, 0.f);
                if (n0 + n < Nc) v = *(const float4*)&B[(long long)(n0 + n) * ldb + k0 + kc];
                Bs[kc + 0][n] = v.x;
                Bs[kc + 1][n] = v.y;
                Bs[kc + 2][n] = v.z;
                Bs[kc + 3][n] = v.w;
            }
        }
        __syncthreads();

        #pragma unroll
        for (int kk = 0; kk < BK; kk++) {
            float a[TM], b[TN];
            #pragma unroll
            for (int h = 0; h < TM / 4; h++) {
                float4 v = *(const float4*)&As[kk][tm * 4 + h * (BM / 2)];
                a[h * 4 + 0] = v.x; a[h * 4 + 1] = v.y;
                a[h * 4 + 2] = v.z; a[h * 4 + 3] = v.w;
            }
            #pragma unroll
            for (int h = 0; h < TN / 4; h++) {
                float4 v = *(const float4*)&Bs[kk][tn * 4 + h * (BN / 2)];
                b[h * 4 + 0] = v.x; b[h * 4 + 1] = v.y;
                b[h * 4 + 2] = v.z; b[h * 4 + 3] = v.w;
            }
            #pragma unroll
            for (int i = 0; i < TM; i++)
                #pragma unroll
                for (int j = 0; j < TN; j++)
                    acc[i][j] += a[i] * b[j];
        }
        __syncthreads();
    }

    #pragma unroll
    for (int i = 0; i < TM; i++) {
        int r = m0 + tm * 4 + (i / 4) * (BM / 2) + (i % 4);
        if (r >= M) continue;
        #pragma unroll
        for (int jh = 0; jh < TN / 4; jh++) {
            int c = n0 + tn * 4 + jh * (BN / 2);
            if (c < Nc) {
                float4 v = make_float4(acc[i][jh * 4 + 0] * alpha, acc[i][jh * 4 + 1] * alpha,
                                       acc[i][jh * 4 + 2] * alpha, acc[i][jh * 4 + 3] * alpha);
                *(float4*)&C[(long long)r * ldc + c] = v;
            }
        }
    }
}

// ----------------------------------------------------------------------------
// Persistent fused neighbor attention. Grid-stride over nodes; each iteration
// prefetches the NEXT node's E tile (mask-predicated) + Qt into registers,
// computes the CURRENT node from smem, then commits the prefetch. Mask ring
// (depth 3) keeps the predicate resident in smem two iterations ahead.
// ----------------------------------------------------------------------------
__global__ void __launch_bounds__(128) attn_kernel(
    const float* __restrict__ hE, const int* __restrict__ mask,
    const float* __restrict__ Qt, float* __restrict__ ctx, int N)
{
    __shared__ float Es[32 * 132];
    __shared__ float Qts[4 * 132];
    __shared__ float Lp[512];
    __shared__ float Asm[128];
    __shared__ int   msk[3][32];

    const int t  = threadIdx.x;
    const int G  = gridDim.x;
    const int n0 = blockIdx.x;
    if (n0 >= N) return;

    // --- prologue: masks for iterations 0 and 1 ---
    if (t < 32) {
        msk[0][t] = mask[(long long)n0 * KNB + t];
        long long n1 = n0 + (long long)G;
        msk[1][t] = (n1 < N) ? mask[n1 * KNB + t] : 0;
    }
    __syncthreads();

    float4 ereg[8];
    float4 qreg;

    // --- prefetch node n0 and commit to smem ---
    {
        const float* e = hE + (long long)n0 * (KNB * HDIM);
        #pragma unroll
        for (int ii = 0; ii < 8; ii++) {
            int idx4 = t + 128 * ii;
            int k = idx4 >> 5;                       // warp-uniform
            ereg[ii] = make_float4(0.f, 0.f, 0.f, 0.f);
            if (msk[0][k]) ereg[ii] = *(const float4*)&e[idx4 << 2];
        }
        qreg = *(const float4*)&Qt[(long long)n0 * 512 + t * 4];
        #pragma unroll
        for (int ii = 0; ii < 8; ii++) {
            int idx4 = t + 128 * ii;
            int k = idx4 >> 5, a4 = idx4 & 31;
            *(float4*)&Es[k * 132 + (a4 << 2)] = ereg[ii];
        }
        int h = t >> 5, a4 = t & 31;
        *(float4*)&Qts[h * 132 + (a4 << 2)] = qreg;
    }
    __syncthreads();

    for (int i = 0; ; i++) {
        const long long n  = n0 + (long long)i * G;
        const long long nn = n + G;
        const bool has_next = (nn < N);
        int mreg = 0;

        // --- phase A: issue prefetch for node nn (results land in regs) ---
        if (has_next) {
            const int s1 = (i + 1) % 3;
            const float* e = hE + nn * (KNB * HDIM);
            #pragma unroll
            for (int ii = 0; ii < 8; ii++) {
                int idx4 = t + 128 * ii;
                int k = idx4 >> 5;                   // warp-uniform
                ereg[ii] = make_float4(0.f, 0.f, 0.f, 0.f);
                if (msk[s1][k]) ereg[ii] = *(const float4*)&e[idx4 << 2];
            }
            qreg = *(const float4*)&Qt[nn * 512 + t * 4];
            if (t < 32) {
                long long n2 = n + 2LL * G;
                mreg = (n2 < N) ? mask[n2 * KNB + t] : 0;
            }
        }

        // --- phase B: compute node n from smem ---
        const int* mc = msk[i % 3];

        {   // logits partials: warp = a-chunk, lane = k
            const int ac = t >> 5;
            const int k  = t & 31;
            const float* ep = &Es[k * 132 + (ac << 5)];
            float p0 = 0.f, p1 = 0.f, p2 = 0.f, p3 = 0.f;
            #pragma unroll
            for (int s = 0; s < 8; s++) {
                float4 e4 = *(const float4*)&ep[s << 2];
                int ao = (ac << 5) + (s << 2);
                float4 q0 = *(const float4*)&Qts[0 * 132 + ao];   // broadcast
                float4 q1 = *(const float4*)&Qts[1 * 132 + ao];
                float4 q2 = *(const float4*)&Qts[2 * 132 + ao];
                float4 q3 = *(const float4*)&Qts[3 * 132 + ao];
                p0 += q0.x * e4.x + q0.y * e4.y + q0.z * e4.z + q0.w * e4.w;
                p1 += q1.x * e4.x + q1.y * e4.y + q1.z * e4.z + q1.w * e4.w;
                p2 += q2.x * e4.x + q2.y * e4.y + q2.z * e4.z + q2.w * e4.w;
                p3 += q3.x * e4.x + q3.y * e4.y + q3.z * e4.z + q3.w * e4.w;
            }
            Lp[(ac << 7) + 0 * 32 + k] = p0;
            Lp[(ac << 7) + 1 * 32 + k] = p1;
            Lp[(ac << 7) + 2 * 32 + k] = p2;
            Lp[(ac << 7) + 3 * 32 + k] = p3;
        }
        __syncthreads();

        {   // masked softmax: warp = head, lane = k
            const int h = t >> 5, k = t & 31;
            float x = Lp[0 * 128 + h * 32 + k] + Lp[1 * 128 + h * 32 + k]
                    + Lp[2 * 128 + h * 32 + k] + Lp[3 * 128 + h * 32 + k];
            bool mv  = (mc[k] != 0);
            float xm = mv ? x : -3.402823466e+38f;
            float mx = xm;
            #pragma unroll
            for (int o = 16; o > 0; o >>= 1) mx = fmaxf(mx, __shfl_xor_sync(0xffffffffu, mx, o));
            float p = mv ? __expf(xm - mx) : 0.f;
            float sm = p;
            #pragma unroll
            for (int o = 16; o > 0; o >>= 1) sm += __shfl_xor_sync(0xffffffffu, sm, o);
            float inv = (sm > 0.f) ? (1.f / sm) : 0.f;
            Asm[h * 32 + k] = p * inv;
        }
        __syncthreads();

        {   // ctx: thread t owns column a = t
            float c0 = 0.f, c1 = 0.f, c2 = 0.f, c3 = 0.f;
            #pragma unroll
            for (int k4 = 0; k4 < 8; k4++) {
                float4 a0 = *(const float4*)&Asm[0 * 32 + (k4 << 2)];
                float4 a1 = *(const float4*)&Asm[1 * 32 + (k4 << 2)];
                float4 a2 = *(const float4*)&Asm[2 * 32 + (k4 << 2)];
                float4 a3 = *(const float4*)&Asm[3 * 32 + (k4 << 2)];
                float w0[4] = {a0.x, a0.y, a0.z, a0.w};
                float w1[4] = {a1.x, a1.y, a1.z, a1.w};
                float w2[4] = {a2.x, a2.y, a2.z, a2.w};
                float w3[4] = {a3.x, a3.y, a3.z, a3.w};
                #pragma unroll
                for (int ii = 0; ii < 4; ii++) {
                    float ev = Es[((k4 << 2) + ii) * 132 + t];
                    c0 += w0[ii] * ev;
                    c1 += w1[ii] * ev;
                    c2 += w2[ii] * ev;
                    c3 += w3[ii] * ev;
                }
            }
            float* cp = ctx + n * 512 + t;
            cp[0]   = c0;
            cp[128] = c1;
            cp[256] = c2;
            cp[384] = c3;
        }

        if (!has_next) break;

        // --- phase C: commit prefetched tile ---
        __syncthreads();
        #pragma unroll
        for (int ii = 0; ii < 8; ii++) {
            int idx4 = t + 128 * ii;
            int k = idx4 >> 5, a4 = idx4 & 31;
            *(float4*)&Es[k * 132 + (a4 << 2)] = ereg[ii];
        }
        {
            int h = t >> 5, a4 = t & 31;
            *(float4*)&Qts[h * 132 + (a4 << 2)] = qreg;
        }
        if (t < 32) msk[(i + 2) % 3][t] = mreg;
        __syncthreads();
    }
}

// ----------------------------------------------------------------------------
extern "C" void kernel_launch(void* const* d_in, const int* in_sizes, int n_in,
                              void* d_out, int out_size)
{
    const float* hV   = (const float*)d_in[0];
    const float* hE   = (const float*)d_in[1];
    const int*   mask = (const int*)  d_in[2];
    const float* WQ   = (const float*)d_in[3];
    const float* WK   = (const float*)d_in[4];
    const float* WV   = (const float*)d_in[5];
    const float* WO   = (const float*)d_in[6];
    float*       out  = (float*)d_out;

    const int N = in_sizes[0] / HDIM;
    if (N <= 0) return;

    float *Q, *Qt, *Ctx, *Vout;
    cudaGetSymbolAddress((void**)&Q,    g_Q);
    cudaGetSymbolAddress((void**)&Qt,   g_Qt);
    cudaGetSymbolAddress((void**)&Ctx,  g_ctx);
    cudaGetSymbolAddress((void**)&Vout, g_vout);

    const int MB64  = (N + 63) / 64;
    const int MB128 = (N + 127) / 128;
    const float inv_sqrt_d = 0.17677669529663687f;  // 1/sqrt(32)

    // 1) Q = h_V @ W_Q^T
    sgemm_kernel<64, 128, 16, 8, 8, true><<<dim3(1, MB64, 1), 128>>>(
        hV, WQ, Q, N, 128, 128, 128, 128, 128, 0, 0, 0, 1.f);

    // 2) Qt[n, h*128+b] = (1/sqrt(d)) * Q[n,32h:32h+32] @ W_K[32h:32h+32,:]
    sgemm_kernel<64, 128, 16, 8, 8, false><<<dim3(1, MB64, 4), 128>>>(
        Q, WK, Qt, N, 128, 32, 128, 128, 512,
        /*aB=*/32, /*bB=*/32 * 128, /*cB=*/128, inv_sqrt_d);

    // 3) persistent fused attention -> ctx[N,512]
    int attn_grid = 888;
    if (attn_grid > N) attn_grid = N;
    attn_kernel<<<attn_grid, 128>>>(hE, mask, Qt, Ctx, N);

    // 4) vout[n, 32h+j] = ctx[n, 128h:] @ W_V[32h+j,:]
    sgemm_kernel<128, 32, 16, 8, 4, true><<<dim3(1, MB128, 4), 128>>>(
        Ctx, WV, Vout, N, 32, 128, 512, 128, 128,
        /*aB=*/128, /*bB=*/32 * 128, /*cB=*/32, 1.f);

    // 5) out = vout @ W_O^T
    sgemm_kernel<64, 128, 16, 8, 8, true><<<dim3(1, MB64, 1), 128>>>(
        Vout, WO, out, N, 128, 128, 128, 128, 128, 0, 0, 0, 1.f);
}